// round 14
// baseline (speedup 1.0000x reference)
#include <cuda_runtime.h>
#include <cuda_bf16.h>
#include <math.h>
#include <stdint.h>

#define NNODES 50000
#define NEDGES 800000
#define MT_PAD 3128          // ceil(50048/16): m16-tiles padded to CTA(128) multiple
#define KT_MAX 16            // K up to 256
#define NT16_MAX 32          // N up to 512
#define SCAN_B 49            // ceil(50000/1024)

// ---------------- scratch (static device globals; no runtime allocation) ----
__device__ float g_xlr[(size_t)NNODES * 512];   // fused [xl | xr] gemm output
__device__ float g_h  [(size_t)NNODES * 256];   // layer-3 activations
// fragment-major bf16 operands (hi/lo split); tail blocks stay 0 from init
__device__ uint4 g_Ah[(size_t)MT_PAD * KT_MAX * 32];
__device__ uint4 g_Al[(size_t)MT_PAD * KT_MAX * 32];
__device__ uint4 g_Bh[(size_t)NT16_MAX * KT_MAX * 32];
__device__ uint4 g_Bl[(size_t)NT16_MAX * KT_MAX * 32];
__device__ int   g_deg [NNODES + 1];
__device__ int   g_rowp[NNODES + 1];
__device__ int   g_pos [NNODES];
__device__ int   g_bsum[64];
__device__ int   g_csrc[NEDGES];

// ======================= helpers ============================================
__device__ __forceinline__ uint32_t pack_bf16(float a, float b) { // a->low, b->high
    __nv_bfloat162 t;
    t.x = __float2bfloat16(a);
    t.y = __float2bfloat16(b);
    return *reinterpret_cast<uint32_t*>(&t);
}

__device__ __forceinline__ void mma16816(float* d, const uint4& a,
                                         uint32_t b0, uint32_t b1) {
    asm volatile(
        "mma.sync.aligned.m16n8k16.row.col.f32.bf16.bf16.f32 "
        "{%0,%1,%2,%3}, {%4,%5,%6,%7}, {%8,%9}, {%0,%1,%2,%3};"
        : "+f"(d[0]), "+f"(d[1]), "+f"(d[2]), "+f"(d[3])
        : "r"(a.x), "r"(a.y), "r"(a.z), "r"(a.w), "r"(b0), "r"(b1));
}

// ======================= CSR build ==========================================
__global__ void zero_deg_kernel(int* __restrict__ deg, int n) {
    int i = blockIdx.x * blockDim.x + threadIdx.x;
    if (i <= n) deg[i] = 0;
}

__global__ void hist_kernel(const int* __restrict__ dst, int* __restrict__ deg, int E) {
    int i = blockIdx.x * blockDim.x + threadIdx.x;
    if (i < E) atomicAdd(&deg[dst[i]], 1);
}

__global__ __launch_bounds__(1024) void scan1_kernel(
    const int* __restrict__ deg, int* __restrict__ rowp,
    int* __restrict__ bsum, int n)
{
    __shared__ int ws[32];
    int i = blockIdx.x * 1024 + threadIdx.x;
    int lane = threadIdx.x & 31, w = threadIdx.x >> 5;
    int v = (i < n) ? deg[i] : 0;
    int x = v;
#pragma unroll
    for (int o = 1; o < 32; o <<= 1) {
        int t = __shfl_up_sync(0xffffffffu, x, o);
        if (lane >= o) x += t;
    }
    if (lane == 31) ws[w] = x;
    __syncthreads();
    if (w == 0) {
        int y = ws[lane];
#pragma unroll
        for (int o = 1; o < 32; o <<= 1) {
            int t = __shfl_up_sync(0xffffffffu, y, o);
            if (lane >= o) y += t;
        }
        ws[lane] = y;
    }
    __syncthreads();
    int excl = x - v + (w ? ws[w - 1] : 0);
    if (i < n) rowp[i] = excl;
    if (threadIdx.x == 0) bsum[blockIdx.x] = ws[31];
}

__global__ void scan2_kernel(int* __restrict__ bsum, int nb) {
    __shared__ int sh[64];
    int t = threadIdx.x;
    int orig = (t < nb) ? bsum[t] : 0;
    sh[t] = orig;
    __syncthreads();
#pragma unroll
    for (int o = 1; o < 64; o <<= 1) {
        int v = (t >= o) ? sh[t - o] : 0;
        __syncthreads();
        sh[t] += v;
        __syncthreads();
    }
    bsum[t] = sh[t] - orig;
}

__global__ __launch_bounds__(1024) void scan3_kernel(
    int* __restrict__ rowp, int* __restrict__ pos,
    const int* __restrict__ bsum, int n, int E)
{
    int i = blockIdx.x * 1024 + threadIdx.x;
    if (i < n) {
        int r = rowp[i] + bsum[blockIdx.x];
        rowp[i] = r;
        pos[i]  = r;
    }
    if (i == 0) rowp[n] = E;
}

__global__ void fillcsr_kernel(const int* __restrict__ src, const int* __restrict__ dst,
                               int* __restrict__ pos, int* __restrict__ csrc, int E) {
    int i = blockIdx.x * blockDim.x + threadIdx.x;
    if (i < E) {
        int p = atomicAdd(&pos[dst[i]], 1);
        csrc[p] = src[i];
    }
}

// ========== A split+pack: fp32 [M][K] -> hi/lo bf16 fragment-major ==========
__global__ void splitA_frag(const float* __restrict__ A,
                            uint4* __restrict__ Ah, uint4* __restrict__ Al,
                            int M, int Kt) {
    int i = blockIdx.x * blockDim.x + threadIdx.x;
    int blk = i >> 5, lane = i & 31;
    int mt = blk / Kt, kt = blk - mt * Kt;
    if (mt >= MT_PAD) return;
    int g = lane >> 2, l = lane & 3;
    int K = Kt * 16;
    int r0 = mt * 16 + g, r1 = r0 + 8;
    int c0 = kt * 16 + 2 * l, c2 = c0 + 8;

    float2 v00 = make_float2(0.f, 0.f), v10 = v00, v02 = v00, v12 = v00;
    if (r0 < M) {
        v00 = *(const float2*)(A + (size_t)r0 * K + c0);
        v02 = *(const float2*)(A + (size_t)r0 * K + c2);
    }
    if (r1 < M) {
        v10 = *(const float2*)(A + (size_t)r1 * K + c0);
        v12 = *(const float2*)(A + (size_t)r1 * K + c2);
    }

    float h00x = __bfloat162float(__float2bfloat16(v00.x));
    float h00y = __bfloat162float(__float2bfloat16(v00.y));
    float h10x = __bfloat162float(__float2bfloat16(v10.x));
    float h10y = __bfloat162float(__float2bfloat16(v10.y));
    float h02x = __bfloat162float(__float2bfloat16(v02.x));
    float h02y = __bfloat162float(__float2bfloat16(v02.y));
    float h12x = __bfloat162float(__float2bfloat16(v12.x));
    float h12y = __bfloat162float(__float2bfloat16(v12.y));

    uint4 hi, lo;
    hi.x = pack_bf16(v00.x, v00.y);
    hi.y = pack_bf16(v10.x, v10.y);
    hi.z = pack_bf16(v02.x, v02.y);
    hi.w = pack_bf16(v12.x, v12.y);
    lo.x = pack_bf16(v00.x - h00x, v00.y - h00y);
    lo.y = pack_bf16(v10.x - h10x, v10.y - h10y);
    lo.z = pack_bf16(v02.x - h02x, v02.y - h02y);
    lo.w = pack_bf16(v12.x - h12x, v12.y - h12y);

    size_t off = (size_t)blk * 32 + lane;
    Ah[off] = hi;
    Al[off] = lo;
}

// ========== B pack: [Wl|Wr] ([K][HC] each) -> hi/lo fragment-major ==========
__global__ void packB_frag(const float* __restrict__ Wl, const float* __restrict__ Wr,
                           uint4* __restrict__ Bh, uint4* __restrict__ Bl,
                           int Kt, int HC) {
    int i = blockIdx.x * blockDim.x + threadIdx.x;
    int blk = i >> 5, lane = i & 31;
    int nt16 = blk / Kt, kt = blk - nt16 * Kt;
    int N2 = 2 * HC;
    if (nt16 * 16 >= N2) return;
    int g = lane >> 2, l = lane & 3;
    int k0 = kt * 16 + 2 * l;

    uint4 hi, lo;
    uint32_t* hp = &hi.x;
    uint32_t* lp = &lo.x;
#pragma unroll
    for (int half = 0; half < 2; half++) {
        int col = nt16 * 16 + half * 8 + g;
        const float* Wt = (col < HC) ? Wl : Wr;
        int c = (col < HC) ? col : col - HC;
#pragma unroll
        for (int r = 0; r < 2; r++) {
            int k = k0 + r * 8;
            float a = Wt[(size_t)k * HC + c];
            float b = Wt[(size_t)(k + 1) * HC + c];
            float ha = __bfloat162float(__float2bfloat16(a));
            float hb = __bfloat162float(__float2bfloat16(b));
            hp[half * 2 + r] = pack_bf16(a, b);
            lp[half * 2 + r] = pack_bf16(a - ha, b - hb);
        }
    }
    size_t off = (size_t)blk * 32 + lane;
    Bh[off] = hi;
    Bl[off] = lo;
}

// ======================= HMMA GEMM (3-term bf16 split) ======================
// C[M,N2] = (Ah+Al)(Bh+Bl)^T, dropping AlBl. CTA tile 128x64, warp 32x32.
// Kt compile-time: fully unrolled, parity double-buffering. Optional bias.
template <int Kt>
__global__ __launch_bounds__(256, 2) void mma_gemm(
    const uint4* __restrict__ Ah, const uint4* __restrict__ Al,
    const uint4* __restrict__ Bh, const uint4* __restrict__ Bl,
    float* __restrict__ C, const float* __restrict__ bias2, int M, int N2)
{
    const int tid = threadIdx.x;
    const int wid = tid >> 5, lane = tid & 31;
    const int g = lane >> 2, l = lane & 3;
    const int mw = wid & 3, nw = wid >> 2;      // 4 x 2 warp grid

    const int mt0  = blockIdx.y * 8 + mw * 2;   // 2 m16 tiles per warp
    const int nt0  = blockIdx.x * 4 + nw * 2;   // 2 n16 tiles per warp

    float acc[2][4][4];
#pragma unroll
    for (int i = 0; i < 2; i++)
#pragma unroll
        for (int j = 0; j < 4; j++)
#pragma unroll
            for (int r = 0; r < 4; r++) acc[i][j][r] = 0.f;

    const uint4* pa0 = Ah + ((size_t)(mt0)     * Kt) * 32 + lane;
    const uint4* pa1 = Ah + ((size_t)(mt0 + 1) * Kt) * 32 + lane;
    const uint4* qa0 = Al + ((size_t)(mt0)     * Kt) * 32 + lane;
    const uint4* qa1 = Al + ((size_t)(mt0 + 1) * Kt) * 32 + lane;
    const uint4* pb0 = Bh + ((size_t)(nt0)     * Kt) * 32 + lane;
    const uint4* pb1 = Bh + ((size_t)(nt0 + 1) * Kt) * 32 + lane;
    const uint4* qb0 = Bl + ((size_t)(nt0)     * Kt) * 32 + lane;
    const uint4* qb1 = Bl + ((size_t)(nt0 + 1) * Kt) * 32 + lane;

    uint4 ah[2][2], al[2][2], bh[2][2], bl[2][2];
    ah[0][0] = pa0[0]; ah[0][1] = pa1[0];
    al[0][0] = qa0[0]; al[0][1] = qa1[0];
    bh[0][0] = pb0[0]; bh[0][1] = pb1[0];
    bl[0][0] = qb0[0]; bl[0][1] = qb1[0];

#pragma unroll
    for (int kt = 0; kt < Kt; kt++) {
        const int cur = kt & 1, nxt = cur ^ 1;
        if (kt + 1 < Kt) {
            ah[nxt][0] = pa0[(kt + 1) * 32]; ah[nxt][1] = pa1[(kt + 1) * 32];
            al[nxt][0] = qa0[(kt + 1) * 32]; al[nxt][1] = qa1[(kt + 1) * 32];
            bh[nxt][0] = pb0[(kt + 1) * 32]; bh[nxt][1] = pb1[(kt + 1) * 32];
            bl[nxt][0] = qb0[(kt + 1) * 32]; bl[nxt][1] = qb1[(kt + 1) * 32];
        }

        // term AhBh
#pragma unroll
        for (int i = 0; i < 2; i++)
#pragma unroll
            for (int j = 0; j < 2; j++) {
                mma16816(acc[i][2 * j],     ah[cur][i], bh[cur][j].x, bh[cur][j].y);
                mma16816(acc[i][2 * j + 1], ah[cur][i], bh[cur][j].z, bh[cur][j].w);
            }
        // term AhBl
#pragma unroll
        for (int i = 0; i < 2; i++)
#pragma unroll
            for (int j = 0; j < 2; j++) {
                mma16816(acc[i][2 * j],     ah[cur][i], bl[cur][j].x, bl[cur][j].y);
                mma16816(acc[i][2 * j + 1], ah[cur][i], bl[cur][j].z, bl[cur][j].w);
            }
        // term AlBh
#pragma unroll
        for (int i = 0; i < 2; i++)
#pragma unroll
            for (int j = 0; j < 2; j++) {
                mma16816(acc[i][2 * j],     al[cur][i], bh[cur][j].x, bh[cur][j].y);
                mma16816(acc[i][2 * j + 1], al[cur][i], bh[cur][j].z, bh[cur][j].w);
            }
    }

    // epilogue
#pragma unroll
    for (int i = 0; i < 2; i++) {
        int rbase = (mt0 + i) * 16;
#pragma unroll
        for (int j = 0; j < 4; j++) {
            int col = (nt0 + (j >> 1)) * 16 + (j & 1) * 8 + 2 * l;
            float b0 = 0.f, b1 = 0.f;
            if (bias2) { b0 = bias2[col]; b1 = bias2[col + 1]; }
            int r0 = rbase + g, r1 = rbase + g + 8;
            if (r0 < M)
                *(float2*)(C + (size_t)r0 * N2 + col) =
                    make_float2(acc[i][j][0] + b0, acc[i][j][1] + b1);
            if (r1 < M)
                *(float2*)(C + (size_t)r1 * N2 + col) =
                    make_float2(acc[i][j][2] + b0, acc[i][j][3] + b1);
        }
    }
}

// ===== single-exp online softmax update: state (m,s), 4-channel acc ========
#define ONLINE1(m, s, P, accv, plv) do { \
    float _mn = fmaxf(m, P); \
    float _d  = __expf(fminf(m, P) - _mn); \
    float _wo = (m >= P) ? 1.f : _d; \
    float _wn = (m >= P) ? _d : 1.f; \
    s = fmaf(s, _wo, _wn); \
    _Pragma("unroll") \
    for (int _j = 0; _j < 4; _j++) \
        accv[_j] = fmaf(accv[_j], _wo, _wn * plv[_j]); \
    m = _mn; \
} while (0)

// ======== node_agg for layers 1-2 (H=4, C=64, ELU) with frag output =========
// Contiguous-half gather layout: lane i handles channels [4i,4i+4) (head i/16)
// and [128+4i,128+4i+4) (head 2+i/16). The two warp LDG.128s per edge cover
// bytes [0,512) and [512,1024) -> 8 L1 wavefronts/edge instead of 16.
// Two independent online-softmax states per lane; 16-lane butterfly reduce.
__global__ __launch_bounds__(512) void node_agg_frag(
    const float* __restrict__ xlr, const int* __restrict__ rowp,
    const int* __restrict__ csrc, const float* __restrict__ att,
    const float* __restrict__ bias,
    uint4* __restrict__ Ah, uint4* __restrict__ Al, int n)
{
    __shared__ float sv[16][260];   // padded stride

    const int wid = threadIdx.x >> 5, lane = threadIdx.x & 31;
    const int mt = blockIdx.x;
    const int nid = mt * 16 + wid;

    if (nid < n) {
        int row = rowp[nid];
        int end = rowp[nid + 1];

        float rxa[4], rxb[4], ata[4], atb[4];
        {
            const float* xrp = xlr + (size_t)nid * 512 + 256;
            float4 a = *(const float4*)(xrp + 4 * lane);
            float4 b = *(const float4*)(xrp + 128 + 4 * lane);
            rxa[0]=a.x; rxa[1]=a.y; rxa[2]=a.z; rxa[3]=a.w;
            rxb[0]=b.x; rxb[1]=b.y; rxb[2]=b.z; rxb[3]=b.w;
            float4 c = *(const float4*)(att + 4 * lane);
            float4 d = *(const float4*)(att + 128 + 4 * lane);
            ata[0]=c.x; ata[1]=c.y; ata[2]=c.z; ata[3]=c.w;
            atb[0]=d.x; atb[1]=d.y; atb[2]=d.z; atb[3]=d.w;
        }

        float m0 = -INFINITY, s0 = 0.f, m1 = -INFINITY, s1 = 0.f;
        float acca[4], accb[4];
#pragma unroll
        for (int j = 0; j < 4; j++) { acca[j] = 0.f; accb[j] = 0.f; }

#define NAF_EDGE(sidx) do { \
    const float* _p = xlr + (size_t)(sidx) * 512; \
    float4 _u = *(const float4*)(_p + 4 * lane); \
    float4 _v = *(const float4*)(_p + 128 + 4 * lane); \
    float pla[4] = {_u.x, _u.y, _u.z, _u.w}; \
    float plb[4] = {_v.x, _v.y, _v.z, _v.w}; \
    float pa = 0.f, pb = 0.f; \
    _Pragma("unroll") \
    for (int _j = 0; _j < 4; _j++) { \
        float _t = pla[_j] + rxa[_j]; \
        _t = fmaxf(_t, 0.2f * _t); \
        pa = fmaf(ata[_j], _t, pa); \
        float _t2 = plb[_j] + rxb[_j]; \
        _t2 = fmaxf(_t2, 0.2f * _t2); \
        pb = fmaf(atb[_j], _t2, pb); \
    } \
    _Pragma("unroll") \
    for (int _o = 8; _o > 0; _o >>= 1) { \
        pa += __shfl_xor_sync(0xffffffffu, pa, _o); \
        pb += __shfl_xor_sync(0xffffffffu, pb, _o); \
    } \
    ONLINE1(m0, s0, pa, acca, pla); \
    ONLINE1(m1, s1, pb, accb, plb); \
} while (0)

        int i = row;
        for (; i + 2 <= end; i += 2) {
            int e0 = csrc[i], e1 = csrc[i + 1];
            NAF_EDGE(e0);
            NAF_EDGE(e1);
        }
        if (i < end) {
            int e0 = csrc[i];
            NAF_EDGE(e0);
        }
#undef NAF_EDGE

        float inv0 = 1.f / (s0 + 1e-16f);
        float inv1 = 1.f / (s1 + 1e-16f);
        float va[4], vb[4];
#pragma unroll
        for (int j = 0; j < 4; j++) {
            float t = acca[j] * inv0 + bias[4 * lane + j];
            va[j] = t > 0.f ? t : expm1f(t);
            float u = accb[j] * inv1 + bias[128 + 4 * lane + j];
            vb[j] = u > 0.f ? u : expm1f(u);
        }
        *(float4*)&sv[wid][4 * lane]       = make_float4(va[0], va[1], va[2], va[3]);
        *(float4*)&sv[wid][128 + 4 * lane] = make_float4(vb[0], vb[1], vb[2], vb[3]);
    }
    __syncthreads();

    // fragment write: thread (kt = wid, lane) emits one hi + one lo uint4
    {
        const int kt = wid;
        const int g = lane >> 2, l = lane & 3;
        const int c0 = kt * 16 + 2 * l;
        float2 a0 = *(float2*)&sv[g][c0];
        float2 a1 = *(float2*)&sv[g + 8][c0];
        float2 a2 = *(float2*)&sv[g][c0 + 8];
        float2 a3 = *(float2*)&sv[g + 8][c0 + 8];

        uint4 hi, lo;
        hi.x = pack_bf16(a0.x, a0.y);
        hi.y = pack_bf16(a1.x, a1.y);
        hi.z = pack_bf16(a2.x, a2.y);
        hi.w = pack_bf16(a3.x, a3.y);
        lo.x = pack_bf16(a0.x - __bfloat162float(__float2bfloat16(a0.x)),
                         a0.y - __bfloat162float(__float2bfloat16(a0.y)));
        lo.y = pack_bf16(a1.x - __bfloat162float(__float2bfloat16(a1.x)),
                         a1.y - __bfloat162float(__float2bfloat16(a1.y)));
        lo.z = pack_bf16(a2.x - __bfloat162float(__float2bfloat16(a2.x)),
                         a2.y - __bfloat162float(__float2bfloat16(a2.y)));
        lo.w = pack_bf16(a3.x - __bfloat162float(__float2bfloat16(a3.x)),
                         a3.y - __bfloat162float(__float2bfloat16(a3.y)));

        size_t off = ((size_t)mt * 16 + kt) * 32 + lane;
        Ah[off] = hi;
        Al[off] = lo;
    }
}

// ======== node_agg for layer 3 (H=1, C=64, no ELU), plain float output ======
__global__ __launch_bounds__(256) void node_agg_l3(
    const float* __restrict__ xlr, const int* __restrict__ rowp,
    const int* __restrict__ csrc, const float* __restrict__ att,
    const float* __restrict__ bias, float* __restrict__ out, int n)
{
    int nid = blockIdx.x * 8 + (threadIdx.x >> 5);
    if (nid >= n) return;
    int lane = threadIdx.x & 31;

    int row = rowp[nid];
    int end = rowp[nid + 1];

    float rxr[2], ratt[2];
    {
        const float* xrp = xlr + (size_t)nid * 128 + 64 + 2 * lane;
        float2 a = *(const float2*)(xrp);
        rxr[0] = a.x; rxr[1] = a.y;
        float2 c = *(const float2*)(att + 2 * lane);
        ratt[0] = c.x; ratt[1] = c.y;
    }

    float m = -INFINITY, s = 0.f;
    float acc[2] = {0.f, 0.f};

#define L3_EDGE(sidx) do { \
    const float* _p = xlr + (size_t)(sidx) * 128 + 2 * lane; \
    float2 _a = *(const float2*)(_p); \
    float pl[2] = {_a.x, _a.y}; \
    float P = 0.f; \
    _Pragma("unroll") \
    for (int _j = 0; _j < 2; _j++) { \
        float _t = pl[_j] + rxr[_j]; \
        _t = fmaxf(_t, 0.2f * _t); \
        P = fmaf(ratt[_j], _t, P); \
    } \
    _Pragma("unroll") \
    for (int _o = 16; _o > 0; _o >>= 1) \
        P += __shfl_xor_sync(0xffffffffu, P, _o); \
    float _mn = fmaxf(m, P); \
    float _d  = __expf(fminf(m, P) - _mn); \
    float _wo = (m >= P) ? 1.f : _d; \
    float _wn = (m >= P) ? _d : 1.f; \
    s = fmaf(s, _wo, _wn); \
    acc[0] = fmaf(acc[0], _wo, _wn * pl[0]); \
    acc[1] = fmaf(acc[1], _wo, _wn * pl[1]); \
    m = _mn; \
} while (0)

    int i = row;
    for (; i + 2 <= end; i += 2) {
        int e0 = csrc[i], e1 = csrc[i + 1];
        L3_EDGE(e0);
        L3_EDGE(e1);
    }
    if (i < end) {
        int e0 = csrc[i];
        L3_EDGE(e0);
    }
#undef L3_EDGE

    float inv = 1.f / (s + 1e-16f);
    float* op = out + (size_t)nid * 64 + 2 * lane;
    op[0] = acc[0] * inv + bias[2 * lane];
    op[1] = acc[1] * inv + bias[2 * lane + 1];
}

// ======================= host driver =========================================
extern "C" void kernel_launch(void* const* d_in, const int* in_sizes, int n_in,
                              void* d_out, int out_size)
{
    const float* x    = (const float*)d_in[0];
    const float* Wl1  = (const float*)d_in[1];
    const float* Wr1  = (const float*)d_in[2];
    const float* att1 = (const float*)d_in[3];
    const float* b1   = (const float*)d_in[4];
    const float* Wl2  = (const float*)d_in[5];
    const float* Wr2  = (const float*)d_in[6];
    const float* att2 = (const float*)d_in[7];
    const float* b2   = (const float*)d_in[8];
    const float* Wl3  = (const float*)d_in[9];
    const float* Wr3  = (const float*)d_in[10];
    const float* att3 = (const float*)d_in[11];
    const float* b3   = (const float*)d_in[12];
    const float* Wlin = (const float*)d_in[13];
    const float* blin = (const float*)d_in[14];
    const int*   ei   = (const int*)d_in[15];

    const int* src = ei;
    const int* dst = ei + NEDGES;

    void* tp;
    float *xlr, *h;
    uint4 *Ah, *Al, *Bh, *Bl;
    int *deg, *rowp, *pos, *bsum, *csrc;
    cudaGetSymbolAddress(&tp, g_xlr);  xlr  = (float*)tp;
    cudaGetSymbolAddress(&tp, g_h);    h    = (float*)tp;
    cudaGetSymbolAddress(&tp, g_Ah);   Ah   = (uint4*)tp;
    cudaGetSymbolAddress(&tp, g_Al);   Al   = (uint4*)tp;
    cudaGetSymbolAddress(&tp, g_Bh);   Bh   = (uint4*)tp;
    cudaGetSymbolAddress(&tp, g_Bl);   Bl   = (uint4*)tp;
    cudaGetSymbolAddress(&tp, g_deg);  deg  = (int*)tp;
    cudaGetSymbolAddress(&tp, g_rowp); rowp = (int*)tp;
    cudaGetSymbolAddress(&tp, g_pos);  pos  = (int*)tp;
    cudaGetSymbolAddress(&tp, g_bsum); bsum = (int*)tp;
    cudaGetSymbolAddress(&tp, g_csrc); csrc = (int*)tp;

    const int NB8  = (NNODES + 7) / 8;
    const int NB16 = (NNODES + 15) / 16;    // 3125 exact
    const int MTB  = (NNODES + 127) / 128;  // 391 CTA rows

    // ---- kernel order keeps mma_gemm (layer 1) at the profiled slot (#4) ----
    {
        int Kt = 8;
        int athr = MT_PAD * Kt * 32;
        splitA_frag<<<(athr + 255) / 256, 256>>>(x, Ah, Al, NNODES, Kt);        // 1
        int bthr = 32 * Kt * 32;
        packB_frag<<<(bthr + 255) / 256, 256>>>(Wl1, Wr1, Bh, Bl, Kt, 256);     // 2
    }
    zero_deg_kernel<<<(NNODES + 256) / 256, 256>>>(deg, NNODES);                // 3
    mma_gemm<8><<<dim3(8, MTB), 256>>>(Ah, Al, Bh, Bl, xlr, nullptr,
                                       NNODES, 512);                            // 4 <- ncu
    hist_kernel<<<(NEDGES + 255) / 256, 256>>>(dst, deg, NEDGES);               // 5
    scan1_kernel<<<SCAN_B, 1024>>>(deg, rowp, bsum, NNODES);                    // 6
    scan2_kernel<<<1, 64>>>(bsum, SCAN_B);                                      // 7
    scan3_kernel<<<SCAN_B, 1024>>>(rowp, pos, bsum, NNODES, NEDGES);            // 8
    fillcsr_kernel<<<(NEDGES + 255) / 256, 256>>>(src, dst, pos, csrc, NEDGES); // 9

    // ---- Layer 1 aggregation: writes layer-2 A fragments (coalesced) ----
    node_agg_frag<<<NB16, 512>>>(xlr, rowp, csrc, att1, b1, Ah, Al, NNODES);

    // ---- Layer 2: K=256 (Kt=16) -> N2=512, ELU; writes layer-3 fragments ----
    {
        int Kt = 16;
        int bthr = 32 * Kt * 32;
        packB_frag<<<(bthr + 255) / 256, 256>>>(Wl2, Wr2, Bh, Bl, Kt, 256);
        mma_gemm<16><<<dim3(8, MTB), 256>>>(Ah, Al, Bh, Bl, xlr, nullptr,
                                            NNODES, 512);
        node_agg_frag<<<NB16, 512>>>(xlr, rowp, csrc, att2, b2, Ah, Al, NNODES);
    }
    // ---- Layer 3: K=256 (Kt=16) -> N2=128, no activation; writes h ----
    {
        int Kt = 16;
        int bthr = 8 * Kt * 32;
        packB_frag<<<(bthr + 255) / 256, 256>>>(Wl3, Wr3, Bh, Bl, Kt, 64);
        mma_gemm<16><<<dim3(2, MTB), 256>>>(Ah, Al, Bh, Bl, xlr, nullptr,
                                            NNODES, 128);
        node_agg_l3<<<NB8, 256>>>(xlr, rowp, csrc, att3, b3, h, NNODES);
    }

    // ---- Final linear via HMMA: out = h @ Wlin + blin (50000x64 @ 64x64) ----
    {
        int Kt = 4;   // K = 64
        int athr = MT_PAD * Kt * 32;
        splitA_frag<<<(athr + 255) / 256, 256>>>(h, Ah, Al, NNODES, Kt);
        int bthr = 4 * Kt * 32;   // 4 nt16 tiles (64 cols), all map to Wlin
        packB_frag<<<(bthr + 255) / 256, 256>>>(Wlin, Wlin, Bh, Bl, Kt, 64);
        mma_gemm<4><<<dim3(1, MTB), 256>>>(Ah, Al, Bh, Bl, (float*)d_out, blin,
                                           NNODES, 64);
    }
}

// round 15
// speedup vs baseline: 1.1192x; 1.1192x over previous
#include <cuda_runtime.h>
#include <cuda_bf16.h>
#include <math.h>
#include <stdint.h>

#define NNODES 50000
#define NEDGES 800000
#define MT_PAD 3128          // ceil(50048/16): m16-tiles padded to CTA(128) multiple
#define KT_MAX 16            // K up to 256
#define NT16_MAX 32          // N up to 512
#define SCAN_B 49            // ceil(50000/1024)

// ---------------- scratch (static device globals; no runtime allocation) ----
__device__ float g_xlr[(size_t)NNODES * 512];   // fused [xl | xr] gemm output
// fragment-major bf16 operands (hi/lo split); tail blocks stay 0 from init
__device__ uint4 g_Ah[(size_t)MT_PAD * KT_MAX * 32];
__device__ uint4 g_Al[(size_t)MT_PAD * KT_MAX * 32];
__device__ uint4 g_Bh[(size_t)NT16_MAX * KT_MAX * 32];
__device__ uint4 g_Bl[(size_t)NT16_MAX * KT_MAX * 32];
__device__ int   g_deg [NNODES + 1];
__device__ int   g_rowp[NNODES + 1];
__device__ int   g_pos [NNODES];
__device__ int   g_bsum[64];
__device__ int   g_csrc[NEDGES];

// ======================= helpers ============================================
__device__ __forceinline__ uint32_t pack_bf16(float a, float b) { // a->low, b->high
    __nv_bfloat162 t;
    t.x = __float2bfloat16(a);
    t.y = __float2bfloat16(b);
    return *reinterpret_cast<uint32_t*>(&t);
}

__device__ __forceinline__ void mma16816(float* d, const uint4& a,
                                         uint32_t b0, uint32_t b1) {
    asm volatile(
        "mma.sync.aligned.m16n8k16.row.col.f32.bf16.bf16.f32 "
        "{%0,%1,%2,%3}, {%4,%5,%6,%7}, {%8,%9}, {%0,%1,%2,%3};"
        : "+f"(d[0]), "+f"(d[1]), "+f"(d[2]), "+f"(d[3])
        : "r"(a.x), "r"(a.y), "r"(a.z), "r"(a.w), "r"(b0), "r"(b1));
}

// ======================= CSR build ==========================================
__global__ void zero_deg_kernel(int* __restrict__ deg, int n) {
    int i = blockIdx.x * blockDim.x + threadIdx.x;
    if (i <= n) deg[i] = 0;
}

__global__ void hist_kernel(const int* __restrict__ dst, int* __restrict__ deg, int E) {
    int i = blockIdx.x * blockDim.x + threadIdx.x;
    if (i < E) atomicAdd(&deg[dst[i]], 1);
}

__global__ __launch_bounds__(1024) void scan1_kernel(
    const int* __restrict__ deg, int* __restrict__ rowp,
    int* __restrict__ bsum, int n)
{
    __shared__ int ws[32];
    int i = blockIdx.x * 1024 + threadIdx.x;
    int lane = threadIdx.x & 31, w = threadIdx.x >> 5;
    int v = (i < n) ? deg[i] : 0;
    int x = v;
#pragma unroll
    for (int o = 1; o < 32; o <<= 1) {
        int t = __shfl_up_sync(0xffffffffu, x, o);
        if (lane >= o) x += t;
    }
    if (lane == 31) ws[w] = x;
    __syncthreads();
    if (w == 0) {
        int y = ws[lane];
#pragma unroll
        for (int o = 1; o < 32; o <<= 1) {
            int t = __shfl_up_sync(0xffffffffu, y, o);
            if (lane >= o) y += t;
        }
        ws[lane] = y;
    }
    __syncthreads();
    int excl = x - v + (w ? ws[w - 1] : 0);
    if (i < n) rowp[i] = excl;
    if (threadIdx.x == 0) bsum[blockIdx.x] = ws[31];
}

__global__ void scan2_kernel(int* __restrict__ bsum, int nb) {
    __shared__ int sh[64];
    int t = threadIdx.x;
    int orig = (t < nb) ? bsum[t] : 0;
    sh[t] = orig;
    __syncthreads();
#pragma unroll
    for (int o = 1; o < 64; o <<= 1) {
        int v = (t >= o) ? sh[t - o] : 0;
        __syncthreads();
        sh[t] += v;
        __syncthreads();
    }
    bsum[t] = sh[t] - orig;
}

__global__ __launch_bounds__(1024) void scan3_kernel(
    int* __restrict__ rowp, int* __restrict__ pos,
    const int* __restrict__ bsum, int n, int E)
{
    int i = blockIdx.x * 1024 + threadIdx.x;
    if (i < n) {
        int r = rowp[i] + bsum[blockIdx.x];
        rowp[i] = r;
        pos[i]  = r;
    }
    if (i == 0) rowp[n] = E;
}

__global__ void fillcsr_kernel(const int* __restrict__ src, const int* __restrict__ dst,
                               int* __restrict__ pos, int* __restrict__ csrc, int E) {
    int i = blockIdx.x * blockDim.x + threadIdx.x;
    if (i < E) {
        int p = atomicAdd(&pos[dst[i]], 1);
        csrc[p] = src[i];
    }
}

// ========== A split+pack: fp32 [M][K] -> hi/lo bf16 fragment-major ==========
__global__ void splitA_frag(const float* __restrict__ A,
                            uint4* __restrict__ Ah, uint4* __restrict__ Al,
                            int M, int Kt) {
    int i = blockIdx.x * blockDim.x + threadIdx.x;
    int blk = i >> 5, lane = i & 31;
    int mt = blk / Kt, kt = blk - mt * Kt;
    if (mt >= MT_PAD) return;
    int g = lane >> 2, l = lane & 3;
    int K = Kt * 16;
    int r0 = mt * 16 + g, r1 = r0 + 8;
    int c0 = kt * 16 + 2 * l, c2 = c0 + 8;

    float2 v00 = make_float2(0.f, 0.f), v10 = v00, v02 = v00, v12 = v00;
    if (r0 < M) {
        v00 = *(const float2*)(A + (size_t)r0 * K + c0);
        v02 = *(const float2*)(A + (size_t)r0 * K + c2);
    }
    if (r1 < M) {
        v10 = *(const float2*)(A + (size_t)r1 * K + c0);
        v12 = *(const float2*)(A + (size_t)r1 * K + c2);
    }

    float h00x = __bfloat162float(__float2bfloat16(v00.x));
    float h00y = __bfloat162float(__float2bfloat16(v00.y));
    float h10x = __bfloat162float(__float2bfloat16(v10.x));
    float h10y = __bfloat162float(__float2bfloat16(v10.y));
    float h02x = __bfloat162float(__float2bfloat16(v02.x));
    float h02y = __bfloat162float(__float2bfloat16(v02.y));
    float h12x = __bfloat162float(__float2bfloat16(v12.x));
    float h12y = __bfloat162float(__float2bfloat16(v12.y));

    uint4 hi, lo;
    hi.x = pack_bf16(v00.x, v00.y);
    hi.y = pack_bf16(v10.x, v10.y);
    hi.z = pack_bf16(v02.x, v02.y);
    hi.w = pack_bf16(v12.x, v12.y);
    lo.x = pack_bf16(v00.x - h00x, v00.y - h00y);
    lo.y = pack_bf16(v10.x - h10x, v10.y - h10y);
    lo.z = pack_bf16(v02.x - h02x, v02.y - h02y);
    lo.w = pack_bf16(v12.x - h12x, v12.y - h12y);

    size_t off = (size_t)blk * 32 + lane;
    Ah[off] = hi;
    Al[off] = lo;
}

// ========== B pack: [Wl|Wr] ([K][HC] each) -> hi/lo fragment-major ==========
__global__ void packB_frag(const float* __restrict__ Wl, const float* __restrict__ Wr,
                           uint4* __restrict__ Bh, uint4* __restrict__ Bl,
                           int Kt, int HC) {
    int i = blockIdx.x * blockDim.x + threadIdx.x;
    int blk = i >> 5, lane = i & 31;
    int nt16 = blk / Kt, kt = blk - nt16 * Kt;
    int N2 = 2 * HC;
    if (nt16 * 16 >= N2) return;
    int g = lane >> 2, l = lane & 3;
    int k0 = kt * 16 + 2 * l;

    uint4 hi, lo;
    uint32_t* hp = &hi.x;
    uint32_t* lp = &lo.x;
#pragma unroll
    for (int half = 0; half < 2; half++) {
        int col = nt16 * 16 + half * 8 + g;
        const float* Wt = (col < HC) ? Wl : Wr;
        int c = (col < HC) ? col : col - HC;
#pragma unroll
        for (int r = 0; r < 2; r++) {
            int k = k0 + r * 8;
            float a = Wt[(size_t)k * HC + c];
            float b = Wt[(size_t)(k + 1) * HC + c];
            float ha = __bfloat162float(__float2bfloat16(a));
            float hb = __bfloat162float(__float2bfloat16(b));
            hp[half * 2 + r] = pack_bf16(a, b);
            lp[half * 2 + r] = pack_bf16(a - ha, b - hb);
        }
    }
    size_t off = (size_t)blk * 32 + lane;
    Bh[off] = hi;
    Bl[off] = lo;
}

// ======================= HMMA GEMM (3-term bf16 split) ======================
// C[M,N2] = (Ah+Al)(Bh+Bl)^T, dropping AlBl. CTA tile 128x64, warp 32x32.
// Kt compile-time: fully unrolled, parity double-buffering. Optional bias.
template <int Kt>
__global__ __launch_bounds__(256, 2) void mma_gemm(
    const uint4* __restrict__ Ah, const uint4* __restrict__ Al,
    const uint4* __restrict__ Bh, const uint4* __restrict__ Bl,
    float* __restrict__ C, const float* __restrict__ bias2, int M, int N2)
{
    const int tid = threadIdx.x;
    const int wid = tid >> 5, lane = tid & 31;
    const int g = lane >> 2, l = lane & 3;
    const int mw = wid & 3, nw = wid >> 2;      // 4 x 2 warp grid

    const int mt0  = blockIdx.y * 8 + mw * 2;   // 2 m16 tiles per warp
    const int nt0  = blockIdx.x * 4 + nw * 2;   // 2 n16 tiles per warp

    float acc[2][4][4];
#pragma unroll
    for (int i = 0; i < 2; i++)
#pragma unroll
        for (int j = 0; j < 4; j++)
#pragma unroll
            for (int r = 0; r < 4; r++) acc[i][j][r] = 0.f;

    const uint4* pa0 = Ah + ((size_t)(mt0)     * Kt) * 32 + lane;
    const uint4* pa1 = Ah + ((size_t)(mt0 + 1) * Kt) * 32 + lane;
    const uint4* qa0 = Al + ((size_t)(mt0)     * Kt) * 32 + lane;
    const uint4* qa1 = Al + ((size_t)(mt0 + 1) * Kt) * 32 + lane;
    const uint4* pb0 = Bh + ((size_t)(nt0)     * Kt) * 32 + lane;
    const uint4* pb1 = Bh + ((size_t)(nt0 + 1) * Kt) * 32 + lane;
    const uint4* qb0 = Bl + ((size_t)(nt0)     * Kt) * 32 + lane;
    const uint4* qb1 = Bl + ((size_t)(nt0 + 1) * Kt) * 32 + lane;

    uint4 ah[2][2], al[2][2], bh[2][2], bl[2][2];
    ah[0][0] = pa0[0]; ah[0][1] = pa1[0];
    al[0][0] = qa0[0]; al[0][1] = qa1[0];
    bh[0][0] = pb0[0]; bh[0][1] = pb1[0];
    bl[0][0] = qb0[0]; bl[0][1] = qb1[0];

#pragma unroll
    for (int kt = 0; kt < Kt; kt++) {
        const int cur = kt & 1, nxt = cur ^ 1;
        if (kt + 1 < Kt) {
            ah[nxt][0] = pa0[(kt + 1) * 32]; ah[nxt][1] = pa1[(kt + 1) * 32];
            al[nxt][0] = qa0[(kt + 1) * 32]; al[nxt][1] = qa1[(kt + 1) * 32];
            bh[nxt][0] = pb0[(kt + 1) * 32]; bh[nxt][1] = pb1[(kt + 1) * 32];
            bl[nxt][0] = qb0[(kt + 1) * 32]; bl[nxt][1] = qb1[(kt + 1) * 32];
        }

        // term AhBh
#pragma unroll
        for (int i = 0; i < 2; i++)
#pragma unroll
            for (int j = 0; j < 2; j++) {
                mma16816(acc[i][2 * j],     ah[cur][i], bh[cur][j].x, bh[cur][j].y);
                mma16816(acc[i][2 * j + 1], ah[cur][i], bh[cur][j].z, bh[cur][j].w);
            }
        // term AhBl
#pragma unroll
        for (int i = 0; i < 2; i++)
#pragma unroll
            for (int j = 0; j < 2; j++) {
                mma16816(acc[i][2 * j],     ah[cur][i], bl[cur][j].x, bl[cur][j].y);
                mma16816(acc[i][2 * j + 1], ah[cur][i], bl[cur][j].z, bl[cur][j].w);
            }
        // term AlBh
#pragma unroll
        for (int i = 0; i < 2; i++)
#pragma unroll
            for (int j = 0; j < 2; j++) {
                mma16816(acc[i][2 * j],     al[cur][i], bh[cur][j].x, bh[cur][j].y);
                mma16816(acc[i][2 * j + 1], al[cur][i], bh[cur][j].z, bh[cur][j].w);
            }
    }

    // epilogue
#pragma unroll
    for (int i = 0; i < 2; i++) {
        int rbase = (mt0 + i) * 16;
#pragma unroll
        for (int j = 0; j < 4; j++) {
            int col = (nt0 + (j >> 1)) * 16 + (j & 1) * 8 + 2 * l;
            float b0 = 0.f, b1 = 0.f;
            if (bias2) { b0 = bias2[col]; b1 = bias2[col + 1]; }
            int r0 = rbase + g, r1 = rbase + g + 8;
            if (r0 < M)
                *(float2*)(C + (size_t)r0 * N2 + col) =
                    make_float2(acc[i][j][0] + b0, acc[i][j][1] + b1);
            if (r1 < M)
                *(float2*)(C + (size_t)r1 * N2 + col) =
                    make_float2(acc[i][j][2] + b0, acc[i][j][3] + b1);
        }
    }
}

// ============ shared node_agg math macros (proven R13 forms) ================
#define NA_LOAD_PL(dst, sidx, PLc) do { \
    const float* _p = xlr + (size_t)(sidx) * (W2c) + lane * (PLc); \
    if constexpr ((PLc) == 8) { \
        float4 _a = *(const float4*)(_p); \
        float4 _b = *(const float4*)(_p + 4); \
        dst[0]=_a.x; dst[1]=_a.y; dst[2]=_a.z; dst[3]=_a.w; \
        dst[4]=_b.x; dst[5]=_b.y; dst[6]=_b.z; dst[7]=_b.w; \
    } else { \
        float2 _a = *(const float2*)(_p); \
        dst[0]=_a.x; dst[1]=_a.y; \
    } \
} while (0)

#define NA_SCORE(P, pl, PLc, LPHc) do { \
    P = 0.f; \
    _Pragma("unroll") \
    for (int _j = 0; _j < (PLc); _j++) { \
        float _v = pl[_j] + rxr[_j]; \
        _v = fmaxf(_v, 0.2f * _v); \
        P = fmaf(ratt[_j], _v, P); \
    } \
    _Pragma("unroll") \
    for (int _o = (LPHc) / 2; _o > 0; _o >>= 1) \
        P += __shfl_xor_sync(0xffffffffu, P, _o); \
} while (0)

#define NA_ONLINE(P, pl, PLc) do { \
    float _mn = fmaxf(m, P); \
    float _sc = __expf(m - _mn); \
    float _w  = __expf(P - _mn); \
    s = fmaf(s, _sc, _w); \
    _Pragma("unroll") \
    for (int _j = 0; _j < (PLc); _j++) \
        acc[_j] = fmaf(acc[_j], _sc, _w * pl[_j]); \
    m = _mn; \
} while (0)

// ======== node_agg for layers 1-2 (H=4, C=64, ELU) with frag output =========
__global__ __launch_bounds__(512) void node_agg_frag(
    const float* __restrict__ xlr, const int* __restrict__ rowp,
    const int* __restrict__ csrc, const float* __restrict__ att,
    const float* __restrict__ bias,
    uint4* __restrict__ Ah, uint4* __restrict__ Al, int n)
{
    constexpr int HC = 256, W2c = 512, PL = 8, LPH = 8;
    __shared__ float sv[16][260];   // padded stride to spread banks

    const int wid = threadIdx.x >> 5, lane = threadIdx.x & 31;
    const int mt = blockIdx.x;
    const int nid = mt * 16 + wid;

    if (nid < n) {
        int row = rowp[nid];
        int end = rowp[nid + 1];

        float rxr[PL], ratt[PL];
        {
            const float* xrp  = xlr + (size_t)nid * W2c + HC + lane * PL;
            const float* attp = att + lane * PL;
            float4 a = *(const float4*)(xrp);
            float4 b = *(const float4*)(xrp + 4);
            rxr[0]=a.x; rxr[1]=a.y; rxr[2]=a.z; rxr[3]=a.w;
            rxr[4]=b.x; rxr[5]=b.y; rxr[6]=b.z; rxr[7]=b.w;
            float4 c = *(const float4*)(attp);
            float4 d = *(const float4*)(attp + 4);
            ratt[0]=c.x; ratt[1]=c.y; ratt[2]=c.z; ratt[3]=c.w;
            ratt[4]=d.x; ratt[5]=d.y; ratt[6]=d.z; ratt[7]=d.w;
        }

        float m = -INFINITY, s = 0.f;
        float acc[PL];
#pragma unroll
        for (int j = 0; j < PL; j++) acc[j] = 0.f;

        int i = row;
        for (; i + 2 <= end; i += 2) {
            int s0 = csrc[i], s1 = csrc[i + 1];
            float pl0[PL], pl1[PL];
            NA_LOAD_PL(pl0, s0, PL);
            NA_LOAD_PL(pl1, s1, PL);
            float p0, p1;
            NA_SCORE(p0, pl0, PL, LPH);
            NA_SCORE(p1, pl1, PL, LPH);
            NA_ONLINE(p0, pl0, PL);
            NA_ONLINE(p1, pl1, PL);
        }
        if (i < end) {
            int s0 = csrc[i];
            float pl0[PL];
            NA_LOAD_PL(pl0, s0, PL);
            float p0;
            NA_SCORE(p0, pl0, PL, LPH);
            NA_ONLINE(p0, pl0, PL);
        }

        float inv = 1.f / (s + 1e-16f);
        const float* bp = bias + lane * PL;
        float v[PL];
#pragma unroll
        for (int j = 0; j < PL; j++) {
            float t = acc[j] * inv + bp[j];
            v[j] = t > 0.f ? t : expm1f(t);   // ELU
        }
        float* srow = sv[wid] + lane * PL;
        *(float4*)(srow)     = make_float4(v[0], v[1], v[2], v[3]);
        *(float4*)(srow + 4) = make_float4(v[4], v[5], v[6], v[7]);
    }
    __syncthreads();

    // fragment write: thread (kt = wid, lane) emits one hi + one lo uint4
    {
        const int kt = wid;
        const int g = lane >> 2, l = lane & 3;
        const int c0 = kt * 16 + 2 * l;
        float2 a0 = *(float2*)&sv[g][c0];
        float2 a1 = *(float2*)&sv[g + 8][c0];
        float2 a2 = *(float2*)&sv[g][c0 + 8];
        float2 a3 = *(float2*)&sv[g + 8][c0 + 8];

        uint4 hi, lo;
        hi.x = pack_bf16(a0.x, a0.y);
        hi.y = pack_bf16(a1.x, a1.y);
        hi.z = pack_bf16(a2.x, a2.y);
        hi.w = pack_bf16(a3.x, a3.y);
        lo.x = pack_bf16(a0.x - __bfloat162float(__float2bfloat16(a0.x)),
                         a0.y - __bfloat162float(__float2bfloat16(a0.y)));
        lo.y = pack_bf16(a1.x - __bfloat162float(__float2bfloat16(a1.x)),
                         a1.y - __bfloat162float(__float2bfloat16(a1.y)));
        lo.z = pack_bf16(a2.x - __bfloat162float(__float2bfloat16(a2.x)),
                         a2.y - __bfloat162float(__float2bfloat16(a2.y)));
        lo.w = pack_bf16(a3.x - __bfloat162float(__float2bfloat16(a3.x)),
                         a3.y - __bfloat162float(__float2bfloat16(a3.y)));

        size_t off = ((size_t)mt * 16 + kt) * 32 + lane;
        Ah[off] = hi;
        Al[off] = lo;
    }
}

// ======== node_agg layer 3 (H=1, C=64, no ELU) -> Kt=4 frag output ==========
// 512 threads = 16 warps = 16 nodes = one m16 tile. Same staging pattern as
// node_agg_frag; only warps 0-3 emit fragments (Kt = 4).
__global__ __launch_bounds__(512) void node_agg_l3_frag(
    const float* __restrict__ xlr, const int* __restrict__ rowp,
    const int* __restrict__ csrc, const float* __restrict__ att,
    const float* __restrict__ bias,
    uint4* __restrict__ Ah, uint4* __restrict__ Al, int n)
{
    constexpr int HC = 64, W2c = 128, PL = 2, LPH = 32;
    __shared__ float sv[16][68];    // padded stride

    const int wid = threadIdx.x >> 5, lane = threadIdx.x & 31;
    const int mt = blockIdx.x;
    const int nid = mt * 16 + wid;

    if (nid < n) {
        int row = rowp[nid];
        int end = rowp[nid + 1];

        float rxr[PL], ratt[PL];
        {
            const float* xrp  = xlr + (size_t)nid * W2c + HC + lane * PL;
            float2 a = *(const float2*)(xrp);
            rxr[0] = a.x; rxr[1] = a.y;
            float2 c = *(const float2*)(att + lane * PL);
            ratt[0] = c.x; ratt[1] = c.y;
        }

        float m = -INFINITY, s = 0.f;
        float acc[PL] = {0.f, 0.f};

        int i = row;
        for (; i + 2 <= end; i += 2) {
            int s0 = csrc[i], s1 = csrc[i + 1];
            float pl0[PL], pl1[PL];
            NA_LOAD_PL(pl0, s0, PL);
            NA_LOAD_PL(pl1, s1, PL);
            float p0, p1;
            NA_SCORE(p0, pl0, PL, LPH);
            NA_SCORE(p1, pl1, PL, LPH);
            NA_ONLINE(p0, pl0, PL);
            NA_ONLINE(p1, pl1, PL);
        }
        if (i < end) {
            int s0 = csrc[i];
            float pl0[PL];
            NA_LOAD_PL(pl0, s0, PL);
            float p0;
            NA_SCORE(p0, pl0, PL, LPH);
            NA_ONLINE(p0, pl0, PL);
        }

        float inv = 1.f / (s + 1e-16f);
        float v0 = acc[0] * inv + bias[2 * lane];
        float v1 = acc[1] * inv + bias[2 * lane + 1];
        *(float2*)&sv[wid][2 * lane] = make_float2(v0, v1);
    }
    __syncthreads();

    // fragment write (Kt = 4): warps 0-3 -> kt; one hi + one lo uint4 each
    if (wid < 4) {
        const int kt = wid;
        const int g = lane >> 2, l = lane & 3;
        const int c0 = kt * 16 + 2 * l;
        float2 a0 = *(float2*)&sv[g][c0];
        float2 a1 = *(float2*)&sv[g + 8][c0];
        float2 a2 = *(float2*)&sv[g][c0 + 8];
        float2 a3 = *(float2*)&sv[g + 8][c0 + 8];

        uint4 hi, lo;
        hi.x = pack_bf16(a0.x, a0.y);
        hi.y = pack_bf16(a1.x, a1.y);
        hi.z = pack_bf16(a2.x, a2.y);
        hi.w = pack_bf16(a3.x, a3.y);
        lo.x = pack_bf16(a0.x - __bfloat162float(__float2bfloat16(a0.x)),
                         a0.y - __bfloat162float(__float2bfloat16(a0.y)));
        lo.y = pack_bf16(a1.x - __bfloat162float(__float2bfloat16(a1.x)),
                         a1.y - __bfloat162float(__float2bfloat16(a1.y)));
        lo.z = pack_bf16(a2.x - __bfloat162float(__float2bfloat16(a2.x)),
                         a2.y - __bfloat162float(__float2bfloat16(a2.y)));
        lo.w = pack_bf16(a3.x - __bfloat162float(__float2bfloat16(a3.x)),
                         a3.y - __bfloat162float(__float2bfloat16(a3.y)));

        size_t off = ((size_t)mt * 4 + kt) * 32 + lane;
        Ah[off] = hi;
        Al[off] = lo;
    }
}

// ======================= host driver =========================================
extern "C" void kernel_launch(void* const* d_in, const int* in_sizes, int n_in,
                              void* d_out, int out_size)
{
    const float* x    = (const float*)d_in[0];
    const float* Wl1  = (const float*)d_in[1];
    const float* Wr1  = (const float*)d_in[2];
    const float* att1 = (const float*)d_in[3];
    const float* b1   = (const float*)d_in[4];
    const float* Wl2  = (const float*)d_in[5];
    const float* Wr2  = (const float*)d_in[6];
    const float* att2 = (const float*)d_in[7];
    const float* b2   = (const float*)d_in[8];
    const float* Wl3  = (const float*)d_in[9];
    const float* Wr3  = (const float*)d_in[10];
    const float* att3 = (const float*)d_in[11];
    const float* b3   = (const float*)d_in[12];
    const float* Wlin = (const float*)d_in[13];
    const float* blin = (const float*)d_in[14];
    const int*   ei   = (const int*)d_in[15];

    const int* src = ei;
    const int* dst = ei + NEDGES;

    void* tp;
    float* xlr;
    uint4 *Ah, *Al, *Bh, *Bl;
    int *deg, *rowp, *pos, *bsum, *csrc;
    cudaGetSymbolAddress(&tp, g_xlr);  xlr  = (float*)tp;
    cudaGetSymbolAddress(&tp, g_Ah);   Ah   = (uint4*)tp;
    cudaGetSymbolAddress(&tp, g_Al);   Al   = (uint4*)tp;
    cudaGetSymbolAddress(&tp, g_Bh);   Bh   = (uint4*)tp;
    cudaGetSymbolAddress(&tp, g_Bl);   Bl   = (uint4*)tp;
    cudaGetSymbolAddress(&tp, g_deg);  deg  = (int*)tp;
    cudaGetSymbolAddress(&tp, g_rowp); rowp = (int*)tp;
    cudaGetSymbolAddress(&tp, g_pos);  pos  = (int*)tp;
    cudaGetSymbolAddress(&tp, g_bsum); bsum = (int*)tp;
    cudaGetSymbolAddress(&tp, g_csrc); csrc = (int*)tp;

    const int NB16 = (NNODES + 15) / 16;    // 3125 exact
    const int MTB  = (NNODES + 127) / 128;  // 391 CTA rows

    // ---- kernel order keeps mma_gemm (layer 1) at the profiled slot (#4) ----
    {
        int Kt = 8;
        int athr = MT_PAD * Kt * 32;
        splitA_frag<<<(athr + 255) / 256, 256>>>(x, Ah, Al, NNODES, Kt);        // 1
        int bthr = 32 * Kt * 32;
        packB_frag<<<(bthr + 255) / 256, 256>>>(Wl1, Wr1, Bh, Bl, Kt, 256);     // 2
    }
    zero_deg_kernel<<<(NNODES + 256) / 256, 256>>>(deg, NNODES);                // 3
    mma_gemm<8><<<dim3(8, MTB), 256>>>(Ah, Al, Bh, Bl, xlr, nullptr,
                                       NNODES, 512);                            // 4 <- ncu
    hist_kernel<<<(NEDGES + 255) / 256, 256>>>(dst, deg, NEDGES);               // 5
    scan1_kernel<<<SCAN_B, 1024>>>(deg, rowp, bsum, NNODES);                    // 6
    scan2_kernel<<<1, 64>>>(bsum, SCAN_B);                                      // 7
    scan3_kernel<<<SCAN_B, 1024>>>(rowp, pos, bsum, NNODES, NEDGES);            // 8
    fillcsr_kernel<<<(NEDGES + 255) / 256, 256>>>(src, dst, pos, csrc, NEDGES); // 9

    // ---- Layer 1 aggregation: writes layer-2 A fragments (coalesced) ----
    node_agg_frag<<<NB16, 512>>>(xlr, rowp, csrc, att1, b1, Ah, Al, NNODES);

    // ---- Layer 2: K=256 (Kt=16) -> N2=512, ELU; writes layer-3 fragments ----
    {
        int Kt = 16;
        int bthr = 32 * Kt * 32;
        packB_frag<<<(bthr + 255) / 256, 256>>>(Wl2, Wr2, Bh, Bl, Kt, 256);
        mma_gemm<16><<<dim3(8, MTB), 256>>>(Ah, Al, Bh, Bl, xlr, nullptr,
                                            NNODES, 512);
        node_agg_frag<<<NB16, 512>>>(xlr, rowp, csrc, att2, b2, Ah, Al, NNODES);
    }
    // ---- Layer 3: K=256 (Kt=16) -> N2=128; agg writes final-linear frags ----
    {
        int Kt = 16;
        int bthr = 8 * Kt * 32;
        packB_frag<<<(bthr + 255) / 256, 256>>>(Wl3, Wr3, Bh, Bl, Kt, 64);
        mma_gemm<16><<<dim3(2, MTB), 256>>>(Ah, Al, Bh, Bl, xlr, nullptr,
                                            NNODES, 128);
        node_agg_l3_frag<<<NB16, 512>>>(xlr, rowp, csrc, att3, b3, Ah, Al, NNODES);
    }

    // ---- Final linear via HMMA: out = frag(h) @ Wlin + blin (Kt=4) ----
    {
        int Kt = 4;
        int bthr = 4 * Kt * 32;   // 4 nt16 tiles (64 cols), all map to Wlin
        packB_frag<<<(bthr + 255) / 256, 256>>>(Wlin, Wlin, Bh, Bl, Kt, 64);
        mma_gemm<4><<<dim3(1, MTB), 256>>>(Ah, Al, Bh, Bl, (float*)d_out, blin,
                                           NNODES, 64);
    }
}

// round 16
// speedup vs baseline: 1.1611x; 1.0374x over previous
#include <cuda_runtime.h>
#include <cuda_bf16.h>
#include <math.h>
#include <stdint.h>

#define NNODES 50000
#define NEDGES 800000
#define MT_PAD 3128          // ceil(50048/16): m16-tiles padded to CTA(128) multiple
#define KT_MAX 16            // K up to 256
#define SCAN_B 49            // ceil(50000/1024)

// ---------------- scratch (static device globals; no runtime allocation) ----
__device__ float g_xlr[(size_t)NNODES * 512];   // fused [xl | xr] gemm output
__device__ uint4 g_Ah[(size_t)MT_PAD * KT_MAX * 32];
__device__ uint4 g_Al[(size_t)MT_PAD * KT_MAX * 32];
// per-layer B operand buffers (hi/lo) so all packs can run up front
__device__ uint4 g_Bh1[32 * 8 * 32],  g_Bl1[32 * 8 * 32];
__device__ uint4 g_Bh2[32 * 16 * 32], g_Bl2[32 * 16 * 32];
__device__ uint4 g_Bh3[8 * 16 * 32],  g_Bl3[8 * 16 * 32];
__device__ uint4 g_Bhf[4 * 4 * 32],   g_Blf[4 * 4 * 32];
__device__ int   g_deg [NNODES + 1];
__device__ int   g_rowp[NNODES + 1];
__device__ int   g_pos [NNODES];
__device__ int   g_bsum[64];
__device__ int   g_csrc[NEDGES];

// ======================= helpers ============================================
__device__ __forceinline__ uint32_t pack_bf16(float a, float b) { // a->low, b->high
    __nv_bfloat162 t;
    t.x = __float2bfloat16(a);
    t.y = __float2bfloat16(b);
    return *reinterpret_cast<uint32_t*>(&t);
}

__device__ __forceinline__ void mma16816(float* d, const uint4& a,
                                         uint32_t b0, uint32_t b1) {
    asm volatile(
        "mma.sync.aligned.m16n8k16.row.col.f32.bf16.bf16.f32 "
        "{%0,%1,%2,%3}, {%4,%5,%6,%7}, {%8,%9}, {%0,%1,%2,%3};"
        : "+f"(d[0]), "+f"(d[1]), "+f"(d[2]), "+f"(d[3])
        : "r"(a.x), "r"(a.y), "r"(a.z), "r"(a.w), "r"(b0), "r"(b1));
}

// ======================= device bodies ======================================
__device__ __forceinline__ void hist_dev(const int* __restrict__ dst,
                                         int* __restrict__ deg, int E, int gi) {
    if (gi < E) atomicAdd(&deg[dst[gi]], 1);
}

__device__ __forceinline__ void fillcsr_dev(const int* __restrict__ src,
                                            const int* __restrict__ dst,
                                            int* __restrict__ pos,
                                            int* __restrict__ csrc, int E, int gi) {
    if (gi < E) {
        int p = atomicAdd(&pos[dst[gi]], 1);
        csrc[p] = src[gi];
    }
}

__device__ __forceinline__ void splitA_dev(const float* __restrict__ A,
                                           uint4* __restrict__ Ah,
                                           uint4* __restrict__ Al,
                                           int M, int Kt, int gi) {
    int blk = gi >> 5, lane = gi & 31;
    int mt = blk / Kt, kt = blk - mt * Kt;
    if (mt >= MT_PAD) return;
    int g = lane >> 2, l = lane & 3;
    int K = Kt * 16;
    int r0 = mt * 16 + g, r1 = r0 + 8;
    int c0 = kt * 16 + 2 * l, c2 = c0 + 8;

    float2 v00 = make_float2(0.f, 0.f), v10 = v00, v02 = v00, v12 = v00;
    if (r0 < M) {
        v00 = *(const float2*)(A + (size_t)r0 * K + c0);
        v02 = *(const float2*)(A + (size_t)r0 * K + c2);
    }
    if (r1 < M) {
        v10 = *(const float2*)(A + (size_t)r1 * K + c0);
        v12 = *(const float2*)(A + (size_t)r1 * K + c2);
    }

    float h00x = __bfloat162float(__float2bfloat16(v00.x));
    float h00y = __bfloat162float(__float2bfloat16(v00.y));
    float h10x = __bfloat162float(__float2bfloat16(v10.x));
    float h10y = __bfloat162float(__float2bfloat16(v10.y));
    float h02x = __bfloat162float(__float2bfloat16(v02.x));
    float h02y = __bfloat162float(__float2bfloat16(v02.y));
    float h12x = __bfloat162float(__float2bfloat16(v12.x));
    float h12y = __bfloat162float(__float2bfloat16(v12.y));

    uint4 hi, lo;
    hi.x = pack_bf16(v00.x, v00.y);
    hi.y = pack_bf16(v10.x, v10.y);
    hi.z = pack_bf16(v02.x, v02.y);
    hi.w = pack_bf16(v12.x, v12.y);
    lo.x = pack_bf16(v00.x - h00x, v00.y - h00y);
    lo.y = pack_bf16(v10.x - h10x, v10.y - h10y);
    lo.z = pack_bf16(v02.x - h02x, v02.y - h02y);
    lo.w = pack_bf16(v12.x - h12x, v12.y - h12y);

    size_t off = (size_t)blk * 32 + lane;
    Ah[off] = hi;
    Al[off] = lo;
}

__device__ __forceinline__ void packB_dev(const float* __restrict__ Wl,
                                          const float* __restrict__ Wr,
                                          uint4* __restrict__ Bh,
                                          uint4* __restrict__ Bl,
                                          int Kt, int HC, int gi) {
    int blk = gi >> 5, lane = gi & 31;
    int nt16 = blk / Kt, kt = blk - nt16 * Kt;
    int N2 = 2 * HC;
    if (nt16 * 16 >= N2) return;
    int g = lane >> 2, l = lane & 3;
    int k0 = kt * 16 + 2 * l;

    uint4 hi, lo;
    uint32_t* hp = &hi.x;
    uint32_t* lp = &lo.x;
#pragma unroll
    for (int half = 0; half < 2; half++) {
        int col = nt16 * 16 + half * 8 + g;
        const float* Wt = (col < HC) ? Wl : Wr;
        int c = (col < HC) ? col : col - HC;
#pragma unroll
        for (int r = 0; r < 2; r++) {
            int k = k0 + r * 8;
            float a = Wt[(size_t)k * HC + c];
            float b = Wt[(size_t)(k + 1) * HC + c];
            float ha = __bfloat162float(__float2bfloat16(a));
            float hb = __bfloat162float(__float2bfloat16(b));
            hp[half * 2 + r] = pack_bf16(a, b);
            lp[half * 2 + r] = pack_bf16(a - ha, b - hb);
        }
    }
    size_t off = (size_t)blk * 32 + lane;
    Bh[off] = hi;
    Bl[off] = lo;
}

// ================= HMMA GEMM body (3-term bf16 split, R11 tile) =============
template <int Kt>
__device__ __forceinline__ void mma_body(
    int bx, int by,
    const uint4* __restrict__ Ah, const uint4* __restrict__ Al,
    const uint4* __restrict__ Bh, const uint4* __restrict__ Bl,
    float* __restrict__ C, const float* __restrict__ bias2, int M, int N2)
{
    const int tid = threadIdx.x;
    const int wid = tid >> 5, lane = tid & 31;
    const int g = lane >> 2, l = lane & 3;
    const int mw = wid & 3, nw = wid >> 2;      // 4 x 2 warp grid

    const int mt0  = by * 8 + mw * 2;   // 2 m16 tiles per warp
    const int nt0  = bx * 4 + nw * 2;   // 2 n16 tiles per warp

    float acc[2][4][4];
#pragma unroll
    for (int i = 0; i < 2; i++)
#pragma unroll
        for (int j = 0; j < 4; j++)
#pragma unroll
            for (int r = 0; r < 4; r++) acc[i][j][r] = 0.f;

    const uint4* pa0 = Ah + ((size_t)(mt0)     * Kt) * 32 + lane;
    const uint4* pa1 = Ah + ((size_t)(mt0 + 1) * Kt) * 32 + lane;
    const uint4* qa0 = Al + ((size_t)(mt0)     * Kt) * 32 + lane;
    const uint4* qa1 = Al + ((size_t)(mt0 + 1) * Kt) * 32 + lane;
    const uint4* pb0 = Bh + ((size_t)(nt0)     * Kt) * 32 + lane;
    const uint4* pb1 = Bh + ((size_t)(nt0 + 1) * Kt) * 32 + lane;
    const uint4* qb0 = Bl + ((size_t)(nt0)     * Kt) * 32 + lane;
    const uint4* qb1 = Bl + ((size_t)(nt0 + 1) * Kt) * 32 + lane;

    uint4 ah[2][2], al[2][2], bh[2][2], bl[2][2];
    ah[0][0] = pa0[0]; ah[0][1] = pa1[0];
    al[0][0] = qa0[0]; al[0][1] = qa1[0];
    bh[0][0] = pb0[0]; bh[0][1] = pb1[0];
    bl[0][0] = qb0[0]; bl[0][1] = qb1[0];

#pragma unroll
    for (int kt = 0; kt < Kt; kt++) {
        const int cur = kt & 1, nxt = cur ^ 1;
        if (kt + 1 < Kt) {
            ah[nxt][0] = pa0[(kt + 1) * 32]; ah[nxt][1] = pa1[(kt + 1) * 32];
            al[nxt][0] = qa0[(kt + 1) * 32]; al[nxt][1] = qa1[(kt + 1) * 32];
            bh[nxt][0] = pb0[(kt + 1) * 32]; bh[nxt][1] = pb1[(kt + 1) * 32];
            bl[nxt][0] = qb0[(kt + 1) * 32]; bl[nxt][1] = qb1[(kt + 1) * 32];
        }

        // term AhBh
#pragma unroll
        for (int i = 0; i < 2; i++)
#pragma unroll
            for (int j = 0; j < 2; j++) {
                mma16816(acc[i][2 * j],     ah[cur][i], bh[cur][j].x, bh[cur][j].y);
                mma16816(acc[i][2 * j + 1], ah[cur][i], bh[cur][j].z, bh[cur][j].w);
            }
        // term AhBl
#pragma unroll
        for (int i = 0; i < 2; i++)
#pragma unroll
            for (int j = 0; j < 2; j++) {
                mma16816(acc[i][2 * j],     ah[cur][i], bl[cur][j].x, bl[cur][j].y);
                mma16816(acc[i][2 * j + 1], ah[cur][i], bl[cur][j].z, bl[cur][j].w);
            }
        // term AlBh
#pragma unroll
        for (int i = 0; i < 2; i++)
#pragma unroll
            for (int j = 0; j < 2; j++) {
                mma16816(acc[i][2 * j],     al[cur][i], bh[cur][j].x, bh[cur][j].y);
                mma16816(acc[i][2 * j + 1], al[cur][i], bh[cur][j].z, bh[cur][j].w);
            }
    }

    // epilogue
#pragma unroll
    for (int i = 0; i < 2; i++) {
        int rbase = (mt0 + i) * 16;
#pragma unroll
        for (int j = 0; j < 4; j++) {
            int col = (nt0 + (j >> 1)) * 16 + (j & 1) * 8 + 2 * l;
            float b0 = 0.f, b1 = 0.f;
            if (bias2) { b0 = bias2[col]; b1 = bias2[col + 1]; }
            int r0 = rbase + g, r1 = rbase + g + 8;
            if (r0 < M)
                *(float2*)(C + (size_t)r0 * N2 + col) =
                    make_float2(acc[i][j][0] + b0, acc[i][j][1] + b1);
            if (r1 < M)
                *(float2*)(C + (size_t)r1 * N2 + col) =
                    make_float2(acc[i][j][2] + b0, acc[i][j][3] + b1);
        }
    }
}

// ======================= kernels ============================================
__global__ void zero_deg_kernel(int* __restrict__ deg, int n) {
    int i = blockIdx.x * blockDim.x + threadIdx.x;
    if (i <= n) deg[i] = 0;
}

// merged prep: splitA(L1) interleaved 1:1 with hist, then all 4 packBs.
// requires deg zeroed beforehand (zero_deg_kernel runs first).
__global__ void prep_kernel(
    const float* __restrict__ x,
    const float* __restrict__ Wl1, const float* __restrict__ Wr1,
    const float* __restrict__ Wl2, const float* __restrict__ Wr2,
    const float* __restrict__ Wl3, const float* __restrict__ Wr3,
    const float* __restrict__ Wlin,
    uint4* __restrict__ Ah, uint4* __restrict__ Al,
    uint4* __restrict__ Bh1, uint4* __restrict__ Bl1,
    uint4* __restrict__ Bh2, uint4* __restrict__ Bl2,
    uint4* __restrict__ Bh3, uint4* __restrict__ Bl3,
    uint4* __restrict__ Bhf, uint4* __restrict__ Blf,
    const int* __restrict__ dst, int* __restrict__ deg)
{
    int vb = blockIdx.x;
    int tid = threadIdx.x;
    if (vb < 6256) {                       // interleaved: even=splitA, odd=hist
        if (vb & 1) {
            int hb = vb >> 1;              // 0..3127
            if (hb < 3125) hist_dev(dst, deg, NEDGES, hb * 256 + tid);
        } else {
            splitA_dev(x, Ah, Al, NNODES, 8, (vb >> 1) * 256 + tid);
        }
        return;
    }
    vb -= 6256;
    if (vb < 32) { packB_dev(Wl1, Wr1, Bh1, Bl1, 8, 256, vb * 256 + tid); return; }
    vb -= 32;
    if (vb < 64) { packB_dev(Wl2, Wr2, Bh2, Bl2, 16, 256, vb * 256 + tid); return; }
    vb -= 64;
    if (vb < 16) { packB_dev(Wl3, Wr3, Bh3, Bl3, 16, 64, vb * 256 + tid); return; }
    vb -= 16;
    packB_dev(Wlin, Wlin, Bhf, Blf, 4, 64, vb * 256 + tid);   // 2 blocks
}
#define PREP_BLOCKS (6256 + 32 + 64 + 16 + 2)

__global__ __launch_bounds__(1024) void scan1_kernel(
    const int* __restrict__ deg, int* __restrict__ rowp,
    int* __restrict__ bsum, int n)
{
    __shared__ int ws[32];
    int i = blockIdx.x * 1024 + threadIdx.x;
    int lane = threadIdx.x & 31, w = threadIdx.x >> 5;
    int v = (i < n) ? deg[i] : 0;
    int x = v;
#pragma unroll
    for (int o = 1; o < 32; o <<= 1) {
        int t = __shfl_up_sync(0xffffffffu, x, o);
        if (lane >= o) x += t;
    }
    if (lane == 31) ws[w] = x;
    __syncthreads();
    if (w == 0) {
        int y = ws[lane];
#pragma unroll
        for (int o = 1; o < 32; o <<= 1) {
            int t = __shfl_up_sync(0xffffffffu, y, o);
            if (lane >= o) y += t;
        }
        ws[lane] = y;
    }
    __syncthreads();
    int excl = x - v + (w ? ws[w - 1] : 0);
    if (i < n) rowp[i] = excl;
    if (threadIdx.x == 0) bsum[blockIdx.x] = ws[31];
}

__global__ void scan2_kernel(int* __restrict__ bsum, int nb) {
    __shared__ int sh[64];
    int t = threadIdx.x;
    int orig = (t < nb) ? bsum[t] : 0;
    sh[t] = orig;
    __syncthreads();
#pragma unroll
    for (int o = 1; o < 64; o <<= 1) {
        int v = (t >= o) ? sh[t - o] : 0;
        __syncthreads();
        sh[t] += v;
        __syncthreads();
    }
    bsum[t] = sh[t] - orig;
}

__global__ __launch_bounds__(1024) void scan3_kernel(
    int* __restrict__ rowp, int* __restrict__ pos,
    const int* __restrict__ bsum, int n, int E)
{
    int i = blockIdx.x * 1024 + threadIdx.x;
    if (i < n) {
        int r = rowp[i] + bsum[blockIdx.x];
        rowp[i] = r;
        pos[i]  = r;
    }
    if (i == 0) rowp[n] = E;
}

// merged: mma<8> layer-1 GEMM interleaved 1:1 with fillcsr (independent)
__global__ __launch_bounds__(256, 2) void mma_fill_kernel(
    const uint4* __restrict__ Ah, const uint4* __restrict__ Al,
    const uint4* __restrict__ Bh, const uint4* __restrict__ Bl,
    float* __restrict__ C, int M, int N2,
    const int* __restrict__ src, const int* __restrict__ dst,
    int* __restrict__ pos, int* __restrict__ csrc)
{
    int vb = blockIdx.x;                   // grid = 6256
    if (vb & 1) {
        int fb = vb >> 1;                  // 0..3127
        if (fb < 3125)
            fillcsr_dev(src, dst, pos, csrc, NEDGES, fb * 256 + threadIdx.x);
        return;
    }
    int mb = vb >> 1;                      // 0..3127
    mma_body<8>(mb & 7, mb >> 3, Ah, Al, Bh, Bl, C, nullptr, M, N2);
}

template <int Kt>
__global__ __launch_bounds__(256, 2) void mma_gemm(
    const uint4* __restrict__ Ah, const uint4* __restrict__ Al,
    const uint4* __restrict__ Bh, const uint4* __restrict__ Bl,
    float* __restrict__ C, const float* __restrict__ bias2, int M, int N2)
{
    mma_body<Kt>(blockIdx.x, blockIdx.y, Ah, Al, Bh, Bl, C, bias2, M, N2);
}

// ============ shared node_agg math macros (proven R13 forms) ================
#define NA_LOAD_PL(dst, sidx, PLc) do { \
    const float* _p = xlr + (size_t)(sidx) * (W2c) + lane * (PLc); \
    if constexpr ((PLc) == 8) { \
        float4 _a = *(const float4*)(_p); \
        float4 _b = *(const float4*)(_p + 4); \
        dst[0]=_a.x; dst[1]=_a.y; dst[2]=_a.z; dst[3]=_a.w; \
        dst[4]=_b.x; dst[5]=_b.y; dst[6]=_b.z; dst[7]=_b.w; \
    } else { \
        float2 _a = *(const float2*)(_p); \
        dst[0]=_a.x; dst[1]=_a.y; \
    } \
} while (0)

#define NA_SCORE(P, pl, PLc, LPHc) do { \
    P = 0.f; \
    _Pragma("unroll") \
    for (int _j = 0; _j < (PLc); _j++) { \
        float _v = pl[_j] + rxr[_j]; \
        _v = fmaxf(_v, 0.2f * _v); \
        P = fmaf(ratt[_j], _v, P); \
    } \
    _Pragma("unroll") \
    for (int _o = (LPHc) / 2; _o > 0; _o >>= 1) \
        P += __shfl_xor_sync(0xffffffffu, P, _o); \
} while (0)

#define NA_ONLINE(P, pl, PLc) do { \
    float _mn = fmaxf(m, P); \
    float _sc = __expf(m - _mn); \
    float _w  = __expf(P - _mn); \
    s = fmaf(s, _sc, _w); \
    _Pragma("unroll") \
    for (int _j = 0; _j < (PLc); _j++) \
        acc[_j] = fmaf(acc[_j], _sc, _w * pl[_j]); \
    m = _mn; \
} while (0)

// ======== node_agg for layers 1-2 (H=4, C=64, ELU) with frag output =========
__global__ __launch_bounds__(512) void node_agg_frag(
    const float* __restrict__ xlr, const int* __restrict__ rowp,
    const int* __restrict__ csrc, const float* __restrict__ att,
    const float* __restrict__ bias,
    uint4* __restrict__ Ah, uint4* __restrict__ Al, int n)
{
    constexpr int HC = 256, W2c = 512, PL = 8, LPH = 8;
    __shared__ float sv[16][260];   // padded stride to spread banks

    const int wid = threadIdx.x >> 5, lane = threadIdx.x & 31;
    const int mt = blockIdx.x;
    const int nid = mt * 16 + wid;

    if (nid < n) {
        int row = rowp[nid];
        int end = rowp[nid + 1];

        float rxr[PL], ratt[PL];
        {
            const float* xrp  = xlr + (size_t)nid * W2c + HC + lane * PL;
            const float* attp = att + lane * PL;
            float4 a = *(const float4*)(xrp);
            float4 b = *(const float4*)(xrp + 4);
            rxr[0]=a.x; rxr[1]=a.y; rxr[2]=a.z; rxr[3]=a.w;
            rxr[4]=b.x; rxr[5]=b.y; rxr[6]=b.z; rxr[7]=b.w;
            float4 c = *(const float4*)(attp);
            float4 d = *(const float4*)(attp + 4);
            ratt[0]=c.x; ratt[1]=c.y; ratt[2]=c.z; ratt[3]=c.w;
            ratt[4]=d.x; ratt[5]=d.y; ratt[6]=d.z; ratt[7]=d.w;
        }

        float m = -INFINITY, s = 0.f;
        float acc[PL];
#pragma unroll
        for (int j = 0; j < PL; j++) acc[j] = 0.f;

        int i = row;
        for (; i + 2 <= end; i += 2) {
            int s0 = csrc[i], s1 = csrc[i + 1];
            float pl0[PL], pl1[PL];
            NA_LOAD_PL(pl0, s0, PL);
            NA_LOAD_PL(pl1, s1, PL);
            float p0, p1;
            NA_SCORE(p0, pl0, PL, LPH);
            NA_SCORE(p1, pl1, PL, LPH);
            NA_ONLINE(p0, pl0, PL);
            NA_ONLINE(p1, pl1, PL);
        }
        if (i < end) {
            int s0 = csrc[i];
            float pl0[PL];
            NA_LOAD_PL(pl0, s0, PL);
            float p0;
            NA_SCORE(p0, pl0, PL, LPH);
            NA_ONLINE(p0, pl0, PL);
        }

        float inv = 1.f / (s + 1e-16f);
        const float* bp = bias + lane * PL;
        float v[PL];
#pragma unroll
        for (int j = 0; j < PL; j++) {
            float t = acc[j] * inv + bp[j];
            v[j] = t > 0.f ? t : expm1f(t);   // ELU
        }
        float* srow = sv[wid] + lane * PL;
        *(float4*)(srow)     = make_float4(v[0], v[1], v[2], v[3]);
        *(float4*)(srow + 4) = make_float4(v[4], v[5], v[6], v[7]);
    }
    __syncthreads();

    // fragment write: thread (kt = wid, lane) emits one hi + one lo uint4
    {
        const int kt = wid;
        const int g = lane >> 2, l = lane & 3;
        const int c0 = kt * 16 + 2 * l;
        float2 a0 = *(float2*)&sv[g][c0];
        float2 a1 = *(float2*)&sv[g + 8][c0];
        float2 a2 = *(float2*)&sv[g][c0 + 8];
        float2 a3 = *(float2*)&sv[g + 8][c0 + 8];

        uint4 hi, lo;
        hi.x = pack_bf16(a0.x, a0.y);
        hi.y = pack_bf16(a1.x, a1.y);
        hi.z = pack_bf16(a2.x, a2.y);
        hi.w = pack_bf16(a3.x, a3.y);
        lo.x = pack_bf16(a0.x - __bfloat162float(__float2bfloat16(a0.x)),
                         a0.y - __bfloat162float(__float2bfloat16(a0.y)));
        lo.y = pack_bf16(a1.x - __bfloat162float(__float2bfloat16(a1.x)),
                         a1.y - __bfloat162float(__float2bfloat16(a1.y)));
        lo.z = pack_bf16(a2.x - __bfloat162float(__float2bfloat16(a2.x)),
                         a2.y - __bfloat162float(__float2bfloat16(a2.y)));
        lo.w = pack_bf16(a3.x - __bfloat162float(__float2bfloat16(a3.x)),
                         a3.y - __bfloat162float(__float2bfloat16(a3.y)));

        size_t off = ((size_t)mt * 16 + kt) * 32 + lane;
        Ah[off] = hi;
        Al[off] = lo;
    }
}

// ======== node_agg layer 3 (H=1, C=64, no ELU) -> Kt=4 frag output ==========
__global__ __launch_bounds__(512) void node_agg_l3_frag(
    const float* __restrict__ xlr, const int* __restrict__ rowp,
    const int* __restrict__ csrc, const float* __restrict__ att,
    const float* __restrict__ bias,
    uint4* __restrict__ Ah, uint4* __restrict__ Al, int n)
{
    constexpr int HC = 64, W2c = 128, PL = 2, LPH = 32;
    __shared__ float sv[16][68];    // padded stride

    const int wid = threadIdx.x >> 5, lane = threadIdx.x & 31;
    const int mt = blockIdx.x;
    const int nid = mt * 16 + wid;

    if (nid < n) {
        int row = rowp[nid];
        int end = rowp[nid + 1];

        float rxr[PL], ratt[PL];
        {
            const float* xrp  = xlr + (size_t)nid * W2c + HC + lane * PL;
            float2 a = *(const float2*)(xrp);
            rxr[0] = a.x; rxr[1] = a.y;
            float2 c = *(const float2*)(att + lane * PL);
            ratt[0] = c.x; ratt[1] = c.y;
        }

        float m = -INFINITY, s = 0.f;
        float acc[PL] = {0.f, 0.f};

        int i = row;
        for (; i + 2 <= end; i += 2) {
            int s0 = csrc[i], s1 = csrc[i + 1];
            float pl0[PL], pl1[PL];
            NA_LOAD_PL(pl0, s0, PL);
            NA_LOAD_PL(pl1, s1, PL);
            float p0, p1;
            NA_SCORE(p0, pl0, PL, LPH);
            NA_SCORE(p1, pl1, PL, LPH);
            NA_ONLINE(p0, pl0, PL);
            NA_ONLINE(p1, pl1, PL);
        }
        if (i < end) {
            int s0 = csrc[i];
            float pl0[PL];
            NA_LOAD_PL(pl0, s0, PL);
            float p0;
            NA_SCORE(p0, pl0, PL, LPH);
            NA_ONLINE(p0, pl0, PL);
        }

        float inv = 1.f / (s + 1e-16f);
        float v0 = acc[0] * inv + bias[2 * lane];
        float v1 = acc[1] * inv + bias[2 * lane + 1];
        *(float2*)&sv[wid][2 * lane] = make_float2(v0, v1);
    }
    __syncthreads();

    // fragment write (Kt = 4): warps 0-3 -> kt; one hi + one lo uint4 each
    if (wid < 4) {
        const int kt = wid;
        const int g = lane >> 2, l = lane & 3;
        const int c0 = kt * 16 + 2 * l;
        float2 a0 = *(float2*)&sv[g][c0];
        float2 a1 = *(float2*)&sv[g + 8][c0];
        float2 a2 = *(float2*)&sv[g][c0 + 8];
        float2 a3 = *(float2*)&sv[g + 8][c0 + 8];

        uint4 hi, lo;
        hi.x = pack_bf16(a0.x, a0.y);
        hi.y = pack_bf16(a1.x, a1.y);
        hi.z = pack_bf16(a2.x, a2.y);
        hi.w = pack_bf16(a3.x, a3.y);
        lo.x = pack_bf16(a0.x - __bfloat162float(__float2bfloat16(a0.x)),
                         a0.y - __bfloat162float(__float2bfloat16(a0.y)));
        lo.y = pack_bf16(a1.x - __bfloat162float(__float2bfloat16(a1.x)),
                         a1.y - __bfloat162float(__float2bfloat16(a1.y)));
        lo.z = pack_bf16(a2.x - __bfloat162float(__float2bfloat16(a2.x)),
                         a2.y - __bfloat162float(__float2bfloat16(a2.y)));
        lo.w = pack_bf16(a3.x - __bfloat162float(__float2bfloat16(a3.x)),
                         a3.y - __bfloat162float(__float2bfloat16(a3.y)));

        size_t off = ((size_t)mt * 4 + kt) * 32 + lane;
        Ah[off] = hi;
        Al[off] = lo;
    }
}

// ======================= host driver =========================================
extern "C" void kernel_launch(void* const* d_in, const int* in_sizes, int n_in,
                              void* d_out, int out_size)
{
    const float* x    = (const float*)d_in[0];
    const float* Wl1  = (const float*)d_in[1];
    const float* Wr1  = (const float*)d_in[2];
    const float* att1 = (const float*)d_in[3];
    const float* b1   = (const float*)d_in[4];
    const float* Wl2  = (const float*)d_in[5];
    const float* Wr2  = (const float*)d_in[6];
    const float* att2 = (const float*)d_in[7];
    const float* b2   = (const float*)d_in[8];
    const float* Wl3  = (const float*)d_in[9];
    const float* Wr3  = (const float*)d_in[10];
    const float* att3 = (const float*)d_in[11];
    const float* b3   = (const float*)d_in[12];
    const float* Wlin = (const float*)d_in[13];
    const float* blin = (const float*)d_in[14];
    const int*   ei   = (const int*)d_in[15];

    const int* src = ei;
    const int* dst = ei + NEDGES;

    void* tp;
    float* xlr;
    uint4 *Ah, *Al, *Bh1, *Bl1, *Bh2, *Bl2, *Bh3, *Bl3, *Bhf, *Blf;
    int *deg, *rowp, *pos, *bsum, *csrc;
    cudaGetSymbolAddress(&tp, g_xlr);  xlr  = (float*)tp;
    cudaGetSymbolAddress(&tp, g_Ah);   Ah   = (uint4*)tp;
    cudaGetSymbolAddress(&tp, g_Al);   Al   = (uint4*)tp;
    cudaGetSymbolAddress(&tp, g_Bh1);  Bh1  = (uint4*)tp;
    cudaGetSymbolAddress(&tp, g_Bl1);  Bl1  = (uint4*)tp;
    cudaGetSymbolAddress(&tp, g_Bh2);  Bh2  = (uint4*)tp;
    cudaGetSymbolAddress(&tp, g_Bl2);  Bl2  = (uint4*)tp;
    cudaGetSymbolAddress(&tp, g_Bh3);  Bh3  = (uint4*)tp;
    cudaGetSymbolAddress(&tp, g_Bl3);  Bl3  = (uint4*)tp;
    cudaGetSymbolAddress(&tp, g_Bhf);  Bhf  = (uint4*)tp;
    cudaGetSymbolAddress(&tp, g_Blf);  Blf  = (uint4*)tp;
    cudaGetSymbolAddress(&tp, g_deg);  deg  = (int*)tp;
    cudaGetSymbolAddress(&tp, g_rowp); rowp = (int*)tp;
    cudaGetSymbolAddress(&tp, g_pos);  pos  = (int*)tp;
    cudaGetSymbolAddress(&tp, g_bsum); bsum = (int*)tp;
    cudaGetSymbolAddress(&tp, g_csrc); csrc = (int*)tp;

    const int NB16 = (NNODES + 15) / 16;    // 3125 exact
    const int MTB  = (NNODES + 127) / 128;  // 391 CTA rows

    // 1: deg must be zeroed before prep's hist blocks
    zero_deg_kernel<<<(NNODES + 256) / 256, 256>>>(deg, NNODES);
    // 2: splitA(L1) || hist, then all packBs
    prep_kernel<<<PREP_BLOCKS, 256>>>(x, Wl1, Wr1, Wl2, Wr2, Wl3, Wr3, Wlin,
                                      Ah, Al, Bh1, Bl1, Bh2, Bl2, Bh3, Bl3,
                                      Bhf, Blf, dst, deg);
    // 3-5: prefix scan
    scan1_kernel<<<SCAN_B, 1024>>>(deg, rowp, bsum, NNODES);
    scan2_kernel<<<1, 64>>>(bsum, SCAN_B);
    scan3_kernel<<<SCAN_B, 1024>>>(rowp, pos, bsum, NNODES, NEDGES);
    // 6: layer-1 GEMM || fillcsr
    mma_fill_kernel<<<6256, 256>>>(Ah, Al, Bh1, Bl1, xlr, NNODES, 512,
                                   src, dst, pos, csrc);
    // 7: layer-1 aggregation -> layer-2 A fragments
    node_agg_frag<<<NB16, 512>>>(xlr, rowp, csrc, att1, b1, Ah, Al, NNODES);
    // 8-9: layer 2
    mma_gemm<16><<<dim3(8, MTB), 256>>>(Ah, Al, Bh2, Bl2, xlr, nullptr,
                                        NNODES, 512);
    node_agg_frag<<<NB16, 512>>>(xlr, rowp, csrc, att2, b2, Ah, Al, NNODES);
    // 10-11: layer 3 (agg emits final-linear Kt=4 fragments)
    mma_gemm<16><<<dim3(2, MTB), 256>>>(Ah, Al, Bh3, Bl3, xlr, nullptr,
                                        NNODES, 128);
    node_agg_l3_frag<<<NB16, 512>>>(xlr, rowp, csrc, att3, b3, Ah, Al, NNODES);
    // 12: final linear via HMMA
    mma_gemm<4><<<dim3(1, MTB), 256>>>(Ah, Al, Bhf, Blf, (float*)d_out, blin,
                                       NNODES, 64);
}